// round 9
// baseline (speedup 1.0000x reference)
#include <cuda_runtime.h>
#include <math.h>
#include <stdint.h>

// ---------------- problem constants ----------------
#define BSZ      64
#define T_STEPS  150
#define IN_DIM   120
#define HID      1024
#define OUT_DIM  35
#define NB       8
#define NCOLS    8192          // HID*NB
#define ROWS     9600          // T_STEPS*BSZ
#define TB       32            // (t,b) rows per gemm group (= one ballot word)
#define GROUPS   300           // ROWS/TB
#define SPAD     36            // padded smem row stride (floats); 144B = 9 x 16B slots, gcd(9,32)=1
#define NNZ1P    16            // IN_DIM/NB = 15, padded to 16 (pad entry: idx=0,val=0 -> exact no-op)
#define NNZ2     128           // HID/NB
#define K2_1     8             // NNZ1P/2
#define K2_2     64            // NNZ2/2

// ---------------- scratch (device globals; no allocation allowed) ----------------
__device__ float    g_D   [(size_t)ROWS * NCOLS];        // dense branch-input buffer (reused per layer)
__device__ unsigned g_bits[(size_t)GROUPS * HID];        // spike bitmasks: [group][i], 32 bits = 32 rows
__device__ float    g_sT  [(size_t)GROUPS * HID * TB];   // layer-3 spikes (float) for readout
__device__ float    g_xT  [(size_t)GROUPS * IN_DIM * TB];
__device__ float    g_r   [(size_t)ROWS * OUT_DIM];
__device__ uint4    g_pv1 [K2_1 * NCOLS];                // packed k-pairs: (idx0,val0,idx1,val1), layout [k2][j]
__device__ uint4    g_pv2 [K2_2 * NCOLS];
__device__ uint4    g_pv3 [K2_2 * NCOLS];
__device__ int      g_flag;                              // mask dtype: 0=u8, 1=i32, 2=f32

// ---------------- mask dtype detector ----------------
// Invariant: mask row 0 (layer 1) has exactly 15 ones among IN_DIM=120 entries.
__global__ void detect_mask(const void* m) {
    if (threadIdx.x != 0 || blockIdx.x != 0) return;
    const int*   mi = (const int*)m;
    const float* mf = (const float*)m;
    int  si = 0;   bool oki = true;
    for (int i = 0; i < IN_DIM; i++) { int v = mi[i]; if (v != 0 && v != 1) oki = false; si += v; }
    float sf = 0.f; bool okf = true;
    for (int i = 0; i < IN_DIM; i++) { float v = mf[i]; if (v != 0.f && v != 1.f) okf = false; sf += v; }
    int f = 0;
    if (oki && si == 15) f = 1;
    else if (okf && sf == 15.0f) f = 2;
    g_flag = f;
}

// ---------------- merged CSR build for all 3 layers: warp per output row j ----------------
// Writes uint2 entries into the uint4 k-pair layout: slot = 2*((k>>1)*NCOLS + j) + (k&1).
__device__ __forceinline__ void build_one(const void* mask, const float* __restrict__ w,
                                          uint2* __restrict__ pv2, int j, int lane,
                                          int sdim, int nnz, int flag) {
    int base = 0;
    int iters = (sdim + 31) >> 5;
    for (int it = 0; it < iters; it++) {
        int i = it * 32 + lane;
        bool on = false;
        if (i < sdim) {
            if (flag == 1)      on = ((const int*)mask)[(size_t)j * sdim + i] != 0;
            else if (flag == 2) on = ((const float*)mask)[(size_t)j * sdim + i] != 0.f;
            else                on = ((const unsigned char*)mask)[(size_t)j * sdim + i] != 0;
        }
        unsigned bal = __ballot_sync(0xFFFFFFFFu, on);
        if (on) {
            int k = base + __popc(bal & ((1u << lane) - 1u));
            if (k < nnz)
                pv2[2 * ((size_t)(k >> 1) * NCOLS + j) + (k & 1)] =
                    make_uint2((unsigned)i, __float_as_uint(w[(size_t)j * sdim + i]));
        }
        base += __popc(bal);
    }
    if (lane == 0)
        for (int k = base; k < nnz; k++)
            pv2[2 * ((size_t)(k >> 1) * NCOLS + j) + (k & 1)] = make_uint2(0u, 0u);
}

__global__ void build_all(const void* m1, const float* __restrict__ w1,
                          const void* m2, const float* __restrict__ w2,
                          const void* m3, const float* __restrict__ w3,
                          uint2* pv1, uint2* pv2, uint2* pv3) {
    int gtid  = blockIdx.x * blockDim.x + threadIdx.x;
    int warp  = gtid >> 5;
    int lane  = gtid & 31;
    int layer = warp >> 13;          // NCOLS = 2^13
    int j     = warp & (NCOLS - 1);
    const int f = g_flag;
    if (layer == 0)      build_one(m1, w1, pv1, j, lane, IN_DIM, NNZ1P, f);
    else if (layer == 1) build_one(m2, w2, pv2, j, lane, HID,    NNZ2,  f);
    else                 build_one(m3, w3, pv3, j, lane, HID,    NNZ2,  f);
}

// ---------------- transpose x: [b][t][i] -> xT[group][i][row%32] ----------------
__global__ void transpose_x(const float* __restrict__ x, float* __restrict__ xT) {
    int u = blockIdx.x * blockDim.x + threadIdx.x;
    if (u >= ROWS * IN_DIM) return;
    int row = u / IN_DIM;
    int i   = u - row * IN_DIM;
    int t   = row >> 6;
    int b   = row & 63;
    xT[(size_t)(row >> 5) * (IN_DIM * TB) + i * TB + (row & 31)] =
        x[(size_t)(b * T_STEPS + t) * IN_DIM + i];
}

// ---------------- layer-1 gemm (float input path), 32 rows x 512 cols per block ----------------
__global__ __launch_bounds__(256, 2)
void gemm_float(const float* __restrict__ sT, const uint4* __restrict__ pv,
                const float* __restrict__ bias, float* __restrict__ D) {
    __shared__ __align__(16) float s_sm[IN_DIM * SPAD];
    const int tid = threadIdx.x;
    const int g   = blockIdx.y;

    const float* src = sT + (size_t)g * (IN_DIM * TB);
    for (int u = tid; u < IN_DIM * TB; u += 256)
        s_sm[(u >> 5) * SPAD + (u & 31)] = src[u];
    __syncthreads();

    const int j0 = blockIdx.x * 512 + tid;
    float acc[2][32];
#pragma unroll
    for (int c = 0; c < 2; c++) {
        float bv = bias[j0 + c * 256];
#pragma unroll
        for (int r = 0; r < 32; r++) acc[c][r] = bv;
    }

    uint4 nx[2];
    nx[0] = pv[j0]; nx[1] = pv[j0 + 256];

#pragma unroll 1
    for (int k2 = 0; k2 < K2_1; k2++) {
        uint4 cur[2];
        cur[0] = nx[0]; cur[1] = nx[1];
        if (k2 + 1 < K2_1) {
            nx[0] = pv[(size_t)(k2 + 1) * NCOLS + j0];
            nx[1] = pv[(size_t)(k2 + 1) * NCOLS + j0 + 256];
        }
#pragma unroll
        for (int c = 0; c < 2; c++) {
#pragma unroll
            for (int half = 0; half < 2; half++) {
                unsigned idx = half ? cur[c].z : cur[c].x;
                float    v   = __uint_as_float(half ? cur[c].w : cur[c].y);
                const float4* sp = reinterpret_cast<const float4*>(s_sm + idx * SPAD);
#pragma unroll
                for (int q = 0; q < 8; q++) {
                    float4 a = sp[q];
                    acc[c][q * 4 + 0] += v * a.x;
                    acc[c][q * 4 + 1] += v * a.y;
                    acc[c][q * 4 + 2] += v * a.z;
                    acc[c][q * 4 + 3] += v * a.w;
                }
            }
        }
    }

#pragma unroll
    for (int c = 0; c < 2; c++)
#pragma unroll
        for (int r = 0; r < 32; r++)
            D[(size_t)(g * TB + r) * NCOLS + j0 + c * 256] = acc[c][r];
}

// ---------------- layer-2/3 gemm (binary spike input, 32-bit mask path) ----------------
// Per (k,c): one LDS.32 bitmask + 32 predicated FADDs. Exact.
__global__ __launch_bounds__(256, 2)
void gemm_bits(const unsigned* __restrict__ bitsIn, const uint4* __restrict__ pv,
               const float* __restrict__ bias, float* __restrict__ D) {
    __shared__ unsigned s_bits[HID];
    const int tid = threadIdx.x;
    const int g   = blockIdx.y;

    const unsigned* src = bitsIn + (size_t)g * HID;
    for (int u = tid; u < HID; u += 256) s_bits[u] = src[u];
    __syncthreads();

    const int j0 = blockIdx.x * 512 + tid;
    float acc[2][32];
#pragma unroll
    for (int c = 0; c < 2; c++) {
        float bv = bias[j0 + c * 256];
#pragma unroll
        for (int r = 0; r < 32; r++) acc[c][r] = bv;
    }

    uint4 nx[2];
    nx[0] = pv[j0]; nx[1] = pv[j0 + 256];

#pragma unroll 1
    for (int k2 = 0; k2 < K2_2; k2++) {
        uint4 cur[2];
        cur[0] = nx[0]; cur[1] = nx[1];
        if (k2 + 1 < K2_2) {
            nx[0] = pv[(size_t)(k2 + 1) * NCOLS + j0];
            nx[1] = pv[(size_t)(k2 + 1) * NCOLS + j0 + 256];
        }
#pragma unroll
        for (int c = 0; c < 2; c++) {
            unsigned m0 = s_bits[cur[c].x];
            float    v0 = __uint_as_float(cur[c].y);
            unsigned m1 = s_bits[cur[c].z];
            float    v1 = __uint_as_float(cur[c].w);
#pragma unroll
            for (int r = 0; r < 32; r++)
                if (m0 & (1u << r)) acc[c][r] += v0;
#pragma unroll
            for (int r = 0; r < 32; r++)
                if (m1 & (1u << r)) acc[c][r] += v1;
        }
    }

#pragma unroll
    for (int c = 0; c < 2; c++)
#pragma unroll
        for (int r = 0; r < 32; r++)
            D[(size_t)(g * TB + r) * NCOLS + j0 + c * 256] = acc[c][r];
}

// ---------------- scan producing spike BITMASKS (layers 1,2) ----------------
// Warp = fixed h, 32 consecutive b -> one ballot = one 32-row group word per t.
__global__ __launch_bounds__(256)
void scan_bits(const float* __restrict__ D, const float* __restrict__ tau_m,
               const float* __restrict__ tau_n, unsigned* __restrict__ bitsOut) {
    int tid  = blockIdx.x * 256 + threadIdx.x;      // 0 .. 65535
    int h    = tid >> 6;
    int b    = tid & 63;
    int lane = threadIdx.x & 31;

    float beta[8], omb[8];
#pragma unroll
    for (int n = 0; n < 8; n++) {
        float bb = 1.f / (1.f + expf(-tau_n[h * 8 + n]));
        beta[n] = bb; omb[n] = 1.f - bb;
    }
    float alpha = 1.f / (1.f + expf(-tau_m[h]));
    float oma   = 1.f - alpha;

    float d[8];
#pragma unroll
    for (int n = 0; n < 8; n++) d[n] = 0.f;
    float mem = 0.f, spk = 0.f;

    const float* base = D + (size_t)h * 8;
    float4 n0 = *(const float4*)(base + (size_t)b * NCOLS);
    float4 n1 = *(const float4*)(base + (size_t)b * NCOLS + 4);

    for (int t = 0; t < T_STEPS; t++) {
        float4 q0 = n0, q1 = n1;
        if (t + 1 < T_STEPS) {
            size_t roff = (size_t)((t + 1) * 64 + b) * NCOLS;
            n0 = *(const float4*)(base + roff);
            n1 = *(const float4*)(base + roff + 4);
        }
        d[0] = beta[0] * d[0] + omb[0] * q0.x;
        d[1] = beta[1] * d[1] + omb[1] * q0.y;
        d[2] = beta[2] * d[2] + omb[2] * q0.z;
        d[3] = beta[3] * d[3] + omb[3] * q0.w;
        d[4] = beta[4] * d[4] + omb[4] * q1.x;
        d[5] = beta[5] * d[5] + omb[5] * q1.y;
        d[6] = beta[6] * d[6] + omb[6] * q1.z;
        d[7] = beta[7] * d[7] + omb[7] * q1.w;
        float l = ((d[0] + d[1]) + (d[2] + d[3])) + ((d[4] + d[5]) + (d[6] + d[7]));
        mem = mem * alpha + oma * l - spk;
        bool fired = mem > 1.0f;
        spk = fired ? 1.0f : 0.0f;
        unsigned bal = __ballot_sync(0xFFFFFFFFu, fired);
        if (lane == 0) {
            int grp = (t * 64 + b) >> 5;             // == t*2 + (b>=32)
            bitsOut[(size_t)grp * HID + h] = bal;
        }
    }
}

// ---------------- scan producing FLOAT spikes (layer 3, feeds readout) ----------------
// Same (h fixed per warp, lane=b) mapping -> contiguous 128B spike writes per warp.
__global__ __launch_bounds__(256)
void scan_float(const float* __restrict__ D, const float* __restrict__ tau_m,
                const float* __restrict__ tau_n, float* __restrict__ sOut) {
    int tid = blockIdx.x * 256 + threadIdx.x;
    int h = tid >> 6;
    int b = tid & 63;

    float beta[8], omb[8];
#pragma unroll
    for (int n = 0; n < 8; n++) {
        float bb = 1.f / (1.f + expf(-tau_n[h * 8 + n]));
        beta[n] = bb; omb[n] = 1.f - bb;
    }
    float alpha = 1.f / (1.f + expf(-tau_m[h]));
    float oma   = 1.f - alpha;

    float d[8];
#pragma unroll
    for (int n = 0; n < 8; n++) d[n] = 0.f;
    float mem = 0.f, spk = 0.f;

    const float* base = D + (size_t)h * 8;
    float4 n0 = *(const float4*)(base + (size_t)b * NCOLS);
    float4 n1 = *(const float4*)(base + (size_t)b * NCOLS + 4);

    for (int t = 0; t < T_STEPS; t++) {
        float4 q0 = n0, q1 = n1;
        if (t + 1 < T_STEPS) {
            size_t roff = (size_t)((t + 1) * 64 + b) * NCOLS;
            n0 = *(const float4*)(base + roff);
            n1 = *(const float4*)(base + roff + 4);
        }
        d[0] = beta[0] * d[0] + omb[0] * q0.x;
        d[1] = beta[1] * d[1] + omb[1] * q0.y;
        d[2] = beta[2] * d[2] + omb[2] * q0.z;
        d[3] = beta[3] * d[3] + omb[3] * q0.w;
        d[4] = beta[4] * d[4] + omb[4] * q1.x;
        d[5] = beta[5] * d[5] + omb[5] * q1.y;
        d[6] = beta[6] * d[6] + omb[6] * q1.z;
        d[7] = beta[7] * d[7] + omb[7] * q1.w;
        float l = ((d[0] + d[1]) + (d[2] + d[3])) + ((d[4] + d[5]) + (d[6] + d[7]));
        mem = mem * alpha + oma * l - spk;
        spk = (mem > 1.0f) ? 1.0f : 0.0f;
        int row = t * 64 + b;
        sOut[(size_t)(row >> 5) * (HID * TB) + h * TB + (row & 31)] = spk;
    }
}

// ---------------- readout GEMM: r[row][o] = br[o] + s3[row]·wr[o] ----------------
__global__ __launch_bounds__(256)
void readout_k(const float* __restrict__ sT, const float* __restrict__ wr,
               const float* __restrict__ br, float* __restrict__ rOut) {
    int g = blockIdx.x;
    const float* sg = sT + (size_t)g * (HID * TB);
    for (int p = threadIdx.x; p < OUT_DIM * TB; p += 256) {
        int o  = p >> 5;
        int rr = p & 31;
        const float* wrow = wr + o * HID;
        float s0 = 0.f, s1 = 0.f, s2 = 0.f, s3 = 0.f;
#pragma unroll 2
        for (int i = 0; i < HID; i += 4) {
            s0 += sg[(i + 0) * TB + rr] * wrow[i + 0];
            s1 += sg[(i + 1) * TB + rr] * wrow[i + 1];
            s2 += sg[(i + 2) * TB + rr] * wrow[i + 2];
            s3 += sg[(i + 3) * TB + rr] * wrow[i + 3];
        }
        rOut[(size_t)(g * TB + rr) * OUT_DIM + o] = br[o] + ((s0 + s1) + (s2 + s3));
    }
}

// ---------------- readout leaky scan + mean + log_softmax ----------------
__global__ void final_k(const float* __restrict__ rIn, const float* __restrict__ tau_mr,
                        float* __restrict__ out) {
    int b = blockIdx.x;
    int o = threadIdx.x;                     // blockDim = 64, only o<35 active
    __shared__ float sv[64];
    __shared__ float s_mx, s_ls;
    float acc = 0.f;
    if (o < OUT_DIM) {
        float alpha = 1.f / (1.f + expf(-tau_mr[o]));
        float oma = 1.f - alpha;
        float mr = 0.f;
        for (int t = 0; t < T_STEPS; t++) {
            mr = mr * alpha + oma * rIn[(size_t)(t * 64 + b) * OUT_DIM + o];
            acc += mr;
        }
        acc /= (float)T_STEPS;
    }
    sv[o] = (o < OUT_DIM) ? acc : -1e30f;
    __syncthreads();
    if (o == 0) {
        float m = -1e30f;
        for (int i = 0; i < OUT_DIM; i++) m = fmaxf(m, sv[i]);
        float s = 0.f;
        for (int i = 0; i < OUT_DIM; i++) s += expf(sv[i] - m);
        s_mx = m; s_ls = logf(s);
    }
    __syncthreads();
    if (o < OUT_DIM) out[b * OUT_DIM + o] = sv[o] - s_mx - s_ls;
}

// ---------------- launch ----------------
extern "C" void kernel_launch(void* const* d_in, const int* in_sizes, int n_in,
                              void* d_out, int out_size) {
    (void)in_sizes; (void)n_in; (void)out_size;
    const float* x   = (const float*)d_in[0];
    const float* w1  = (const float*)d_in[1];
    const float* b1  = (const float*)d_in[2];
    const float* tm1 = (const float*)d_in[3];
    const float* tn1 = (const float*)d_in[4];
    const float* w2  = (const float*)d_in[5];
    const float* b2  = (const float*)d_in[6];
    const float* tm2 = (const float*)d_in[7];
    const float* tn2 = (const float*)d_in[8];
    const float* w3  = (const float*)d_in[9];
    const float* b3  = (const float*)d_in[10];
    const float* tm3 = (const float*)d_in[11];
    const float* tn3 = (const float*)d_in[12];
    const float* wr  = (const float*)d_in[13];
    const float* br  = (const float*)d_in[14];
    const float* tmr = (const float*)d_in[15];
    const void*  m1  = d_in[16];
    const void*  m2  = d_in[17];
    const void*  m3  = d_in[18];
    float* out = (float*)d_out;

    void *pD, *pB, *psT, *pxT, *pr, *pv1, *pv2, *pv3;
    cudaGetSymbolAddress(&pD,  g_D);
    cudaGetSymbolAddress(&pB,  g_bits);
    cudaGetSymbolAddress(&psT, g_sT);
    cudaGetSymbolAddress(&pxT, g_xT);
    cudaGetSymbolAddress(&pr,  g_r);
    cudaGetSymbolAddress(&pv1, g_pv1);
    cudaGetSymbolAddress(&pv2, g_pv2);
    cudaGetSymbolAddress(&pv3, g_pv3);

    // 1) mask dtype + merged CSR build (all 3 layers in one latency-overlapped kernel)
    detect_mask<<<1, 32>>>(m1);
    build_all<<<3 * NCOLS * 32 / 256, 256>>>(m1, w1, m2, w2, m3, w3,
                                             (uint2*)pv1, (uint2*)pv2, (uint2*)pv3);

    // 2) input transpose
    transpose_x<<<(ROWS * IN_DIM + 255) / 256, 256>>>(x, (float*)pxT);

    dim3 gg(NCOLS / 512, GROUPS);

    // 3) layer 1 (float input) -> spike bitmasks
    gemm_float<<<gg, 256>>>((const float*)pxT, (const uint4*)pv1, b1, (float*)pD);
    scan_bits<<<(BSZ * HID) / 256, 256>>>((const float*)pD, tm1, tn1, (unsigned*)pB);

    // 4) layer 2 (bitmask input) -> spike bitmasks
    gemm_bits<<<gg, 256>>>((const unsigned*)pB, (const uint4*)pv2, b2, (float*)pD);
    scan_bits<<<(BSZ * HID) / 256, 256>>>((const float*)pD, tm2, tn2, (unsigned*)pB);

    // 5) layer 3 (bitmask input) -> float spikes for readout
    gemm_bits<<<gg, 256>>>((const unsigned*)pB, (const uint4*)pv3, b3, (float*)pD);
    scan_float<<<(BSZ * HID) / 256, 256>>>((const float*)pD, tm3, tn3, (float*)psT);

    // 6) readout + final scan + log_softmax
    readout_k<<<GROUPS, 256>>>((const float*)psT, wr, br, (float*)pr);
    final_k<<<BSZ, 64>>>((const float*)pr, tmr, out);
}

// round 10
// speedup vs baseline: 1.0780x; 1.0780x over previous
#include <cuda_runtime.h>
#include <math.h>
#include <stdint.h>

// ---------------- problem constants ----------------
#define BSZ      64
#define T_STEPS  150
#define IN_DIM   120
#define HID      1024
#define OUT_DIM  35
#define NB       8
#define NCOLS    8192          // HID*NB
#define ROWS     9600          // T_STEPS*BSZ
#define TB       32            // (t,b) rows per gemm group (= one ballot word)
#define GROUPS   300           // ROWS/TB
#define NNZ1P    16            // IN_DIM/NB = 15, padded to 16 (pad entry: idx=0,val=0 -> exact no-op)
#define NNZ2     128           // HID/NB
#define K2_1     8             // NNZ1P/2
#define K2_2     64            // NNZ2/2
#define JT       64            // j-tile per gemm_float block

// ---------------- scratch (device globals; no allocation allowed) ----------------
__device__ float    g_D   [(size_t)ROWS * NCOLS];        // dense branch-input buffer (reused per layer)
__device__ unsigned g_bits[(size_t)GROUPS * HID];        // spike bitmasks: [group][i], 32 bits = 32 rows
__device__ float    g_xT  [(size_t)GROUPS * IN_DIM * TB];
__device__ float    g_r   [(size_t)ROWS * OUT_DIM];
__device__ uint4    g_pv1 [K2_1 * NCOLS];                // packed k-pairs: (idx0,val0,idx1,val1), layout [k2][j]
__device__ uint4    g_pv2 [K2_2 * NCOLS];
__device__ uint4    g_pv3 [K2_2 * NCOLS];
__device__ int      g_flag;                              // mask dtype: 0=u8, 1=i32, 2=f32

// ---------------- mask dtype detector ----------------
// Invariant: mask row 0 (layer 1) has exactly 15 ones among IN_DIM=120 entries.
__global__ void detect_mask(const void* m) {
    if (threadIdx.x != 0 || blockIdx.x != 0) return;
    const int*   mi = (const int*)m;
    const float* mf = (const float*)m;
    int  si = 0;   bool oki = true;
    for (int i = 0; i < IN_DIM; i++) { int v = mi[i]; if (v != 0 && v != 1) oki = false; si += v; }
    float sf = 0.f; bool okf = true;
    for (int i = 0; i < IN_DIM; i++) { float v = mf[i]; if (v != 0.f && v != 1.f) okf = false; sf += v; }
    int f = 0;
    if (oki && si == 15) f = 1;
    else if (okf && sf == 15.0f) f = 2;
    g_flag = f;
}

// ---------------- merged CSR build for all 3 layers: warp per output row j ----------------
__device__ __forceinline__ void build_one(const void* mask, const float* __restrict__ w,
                                          uint2* __restrict__ pv2, int j, int lane,
                                          int sdim, int nnz, int flag) {
    int base = 0;
    int iters = (sdim + 31) >> 5;
    for (int it = 0; it < iters; it++) {
        int i = it * 32 + lane;
        bool on = false;
        if (i < sdim) {
            if (flag == 1)      on = ((const int*)mask)[(size_t)j * sdim + i] != 0;
            else if (flag == 2) on = ((const float*)mask)[(size_t)j * sdim + i] != 0.f;
            else                on = ((const unsigned char*)mask)[(size_t)j * sdim + i] != 0;
        }
        unsigned bal = __ballot_sync(0xFFFFFFFFu, on);
        if (on) {
            int k = base + __popc(bal & ((1u << lane) - 1u));
            if (k < nnz)
                pv2[2 * ((size_t)(k >> 1) * NCOLS + j) + (k & 1)] =
                    make_uint2((unsigned)i, __float_as_uint(w[(size_t)j * sdim + i]));
        }
        base += __popc(bal);
    }
    if (lane == 0)
        for (int k = base; k < nnz; k++)
            pv2[2 * ((size_t)(k >> 1) * NCOLS + j) + (k & 1)] = make_uint2(0u, 0u);
}

__global__ void build_all(const void* m1, const float* __restrict__ w1,
                          const void* m2, const float* __restrict__ w2,
                          const void* m3, const float* __restrict__ w3,
                          uint2* pv1, uint2* pv2, uint2* pv3) {
    int gtid  = blockIdx.x * blockDim.x + threadIdx.x;
    int warp  = gtid >> 5;
    int lane  = gtid & 31;
    int layer = warp >> 13;          // NCOLS = 2^13
    int j     = warp & (NCOLS - 1);
    const int f = g_flag;
    if (layer == 0)      build_one(m1, w1, pv1, j, lane, IN_DIM, NNZ1P, f);
    else if (layer == 1) build_one(m2, w2, pv2, j, lane, HID,    NNZ2,  f);
    else                 build_one(m3, w3, pv3, j, lane, HID,    NNZ2,  f);
}

// ---------------- transpose x: [b][t][i] -> xT[group][i][row%32] ----------------
__global__ void transpose_x(const float* __restrict__ x, float* __restrict__ xT) {
    int u = blockIdx.x * blockDim.x + threadIdx.x;
    if (u >= ROWS * IN_DIM) return;
    int row = u / IN_DIM;
    int i   = u - row * IN_DIM;
    int t   = row >> 6;
    int b   = row & 63;
    xT[(size_t)(row >> 5) * (IN_DIM * TB) + i * TB + (row & 31)] =
        x[(size_t)(b * T_STEPS + t) * IN_DIM + i];
}

// ---------------- layer-1 gemm: warp-uniform j, lane = row (conflict-free) ----------------
// Per (j,k): uniform LDS of (idx,val) -> broadcast; LDS.32 of s_x[idx][lane] -> conflict-free; FFMA.
__global__ __launch_bounds__(256)
void gemm_float(const float* __restrict__ xT, const uint4* __restrict__ pv,
                const float* __restrict__ bias, float* __restrict__ D) {
    __shared__ float s_x[IN_DIM * 33];       // [i][row], stride 33 -> conflict-free
    __shared__ uint4 s_pv[K2_1 * JT];        // [k2][j_local]
    __shared__ float s_b[JT];
    __shared__ float s_d[TB * 33];           // staging; written per-warp-chunk, reused per jj

    const int tid  = threadIdx.x;
    const int lane = tid & 31;
    const int warp = tid >> 5;               // 0..7
    const int g    = blockIdx.y;
    const int jt0  = blockIdx.x * JT;

    // stage x slice [120][32]
    {
        const float* src = xT + (size_t)g * (IN_DIM * TB);
        for (int u = tid; u < IN_DIM * TB; u += 256)
            s_x[(u >> 5) * 33 + (u & 31)] = src[u];
    }
    // stage pv tile [8 k2][64 j]
    for (int u = tid; u < K2_1 * JT; u += 256) {
        int k2 = u >> 6, j = u & (JT - 1);
        s_pv[u] = pv[(size_t)k2 * NCOLS + jt0 + j];
    }
    if (tid < JT) s_b[tid] = bias[jt0 + tid];
    __syncthreads();

    // each warp: 8 j's; lane = row; scalar accumulator
    float accs[8];
#pragma unroll
    for (int jj = 0; jj < 8; jj++) {
        const int jl = warp * 8 + jj;
        float acc = s_b[jl];
#pragma unroll
        for (int k2 = 0; k2 < K2_1; k2++) {
            uint4 p = s_pv[k2 * JT + jl];                 // uniform -> broadcast
            acc += __uint_as_float(p.y) * s_x[p.x * 33 + lane];
            acc += __uint_as_float(p.w) * s_x[p.z * 33 + lane];
        }
        accs[jj] = acc;
    }
    // stage results: s_d layout [j_local][row] with stride 33 — but s_d holds only
    // one 32x64 tile; use [jl*? ] -> need 64*33 floats; reuse trick: write directly
    // via a second smem region sized 64x33.
    __syncthreads();   // s_x no longer needed; but s_d2 is separate — just store
    {
        __shared__ float s_out[JT * 33];
#pragma unroll
        for (int jj = 0; jj < 8; jj++)
            s_out[(warp * 8 + jj) * 33 + lane] = accs[jj];
        __syncthreads();
        // coalesced writeout: row-major, 64 consecutive j per row
        for (int u = tid; u < TB * JT; u += 256) {
            int row = u >> 6;                 // 0..31
            int j   = u & (JT - 1);
            D[(size_t)(g * TB + row) * NCOLS + jt0 + j] = s_out[j * 33 + row];
        }
    }
    (void)s_d;
}

// ---------------- layer-2/3 gemm (binary spike input, 32-bit mask path) ----------------
__global__ __launch_bounds__(256, 2)
void gemm_bits(const unsigned* __restrict__ bitsIn, const uint4* __restrict__ pv,
               const float* __restrict__ bias, float* __restrict__ D) {
    __shared__ unsigned s_bits[HID];
    const int tid = threadIdx.x;
    const int g   = blockIdx.y;

    const unsigned* src = bitsIn + (size_t)g * HID;
    for (int u = tid; u < HID; u += 256) s_bits[u] = src[u];
    __syncthreads();

    const int j0 = blockIdx.x * 512 + tid;
    float acc[2][32];
#pragma unroll
    for (int c = 0; c < 2; c++) {
        float bv = bias[j0 + c * 256];
#pragma unroll
        for (int r = 0; r < 32; r++) acc[c][r] = bv;
    }

    uint4 nx[2];
    nx[0] = pv[j0]; nx[1] = pv[j0 + 256];

#pragma unroll 1
    for (int k2 = 0; k2 < K2_2; k2++) {
        uint4 cur[2];
        cur[0] = nx[0]; cur[1] = nx[1];
        if (k2 + 1 < K2_2) {
            nx[0] = pv[(size_t)(k2 + 1) * NCOLS + j0];
            nx[1] = pv[(size_t)(k2 + 1) * NCOLS + j0 + 256];
        }
#pragma unroll
        for (int c = 0; c < 2; c++) {
            unsigned m0 = s_bits[cur[c].x];
            float    v0 = __uint_as_float(cur[c].y);
            unsigned m1 = s_bits[cur[c].z];
            float    v1 = __uint_as_float(cur[c].w);
#pragma unroll
            for (int r = 0; r < 32; r++)
                if (m0 & (1u << r)) acc[c][r] += v0;
#pragma unroll
            for (int r = 0; r < 32; r++)
                if (m1 & (1u << r)) acc[c][r] += v1;
        }
    }

#pragma unroll
    for (int c = 0; c < 2; c++)
#pragma unroll
        for (int r = 0; r < 32; r++)
            D[(size_t)(g * TB + r) * NCOLS + j0 + c * 256] = acc[c][r];
}

// ---------------- scan producing spike BITMASKS (all 3 layers) ----------------
// Warp = fixed h, 32 consecutive b -> one ballot = one 32-row group word per t.
__global__ __launch_bounds__(256)
void scan_bits(const float* __restrict__ D, const float* __restrict__ tau_m,
               const float* __restrict__ tau_n, unsigned* __restrict__ bitsOut) {
    int tid  = blockIdx.x * 256 + threadIdx.x;      // 0 .. 65535
    int h    = tid >> 6;
    int b    = tid & 63;
    int lane = threadIdx.x & 31;

    float beta[8], omb[8];
#pragma unroll
    for (int n = 0; n < 8; n++) {
        float bb = 1.f / (1.f + expf(-tau_n[h * 8 + n]));
        beta[n] = bb; omb[n] = 1.f - bb;
    }
    float alpha = 1.f / (1.f + expf(-tau_m[h]));
    float oma   = 1.f - alpha;

    float d[8];
#pragma unroll
    for (int n = 0; n < 8; n++) d[n] = 0.f;
    float mem = 0.f, spk = 0.f;

    const float* base = D + (size_t)h * 8;
    float4 n0 = *(const float4*)(base + (size_t)b * NCOLS);
    float4 n1 = *(const float4*)(base + (size_t)b * NCOLS + 4);

    for (int t = 0; t < T_STEPS; t++) {
        float4 q0 = n0, q1 = n1;
        if (t + 1 < T_STEPS) {
            size_t roff = (size_t)((t + 1) * 64 + b) * NCOLS;
            n0 = *(const float4*)(base + roff);
            n1 = *(const float4*)(base + roff + 4);
        }
        d[0] = beta[0] * d[0] + omb[0] * q0.x;
        d[1] = beta[1] * d[1] + omb[1] * q0.y;
        d[2] = beta[2] * d[2] + omb[2] * q0.z;
        d[3] = beta[3] * d[3] + omb[3] * q0.w;
        d[4] = beta[4] * d[4] + omb[4] * q1.x;
        d[5] = beta[5] * d[5] + omb[5] * q1.y;
        d[6] = beta[6] * d[6] + omb[6] * q1.z;
        d[7] = beta[7] * d[7] + omb[7] * q1.w;
        float l = ((d[0] + d[1]) + (d[2] + d[3])) + ((d[4] + d[5]) + (d[6] + d[7]));
        mem = mem * alpha + oma * l - spk;
        bool fired = mem > 1.0f;
        spk = fired ? 1.0f : 0.0f;
        unsigned bal = __ballot_sync(0xFFFFFFFFu, fired);
        if (lane == 0) {
            int grp = (t * 64 + b) >> 5;             // == t*2 + (b>=32)
            bitsOut[(size_t)grp * HID + h] = bal;
        }
    }
}

// ---------------- readout from spike bitmasks: r[row][o] = br[o] + s3[row]·wr[o] ----------------
// Block per group; thread = (o, chunk of 128 i); 32 rows accumulated via predicated adds.
#define RO_THREADS 280          // 35 o x 8 chunks
__global__ __launch_bounds__(RO_THREADS)
void readout_bits(const unsigned* __restrict__ bitsIn, const float* __restrict__ wr,
                  const float* __restrict__ br, float* __restrict__ rOut) {
    __shared__ unsigned s_bits[HID];
    __shared__ float    s_red[RO_THREADS * 32];
    const int tid = threadIdx.x;
    const int g   = blockIdx.x;

    const unsigned* src = bitsIn + (size_t)g * HID;
    for (int u = tid; u < HID; u += RO_THREADS) s_bits[u] = src[u];
    __syncthreads();

    const int o     = tid >> 3;          // 0..34
    const int chunk = tid & 7;           // 0..7
    float acc[32];
#pragma unroll
    for (int r = 0; r < 32; r++) acc[r] = 0.f;

    const float* wrow = wr + o * HID + chunk * 128;
    const unsigned* mb = s_bits + chunk * 128;
#pragma unroll 4
    for (int i = 0; i < 128; i++) {
        unsigned m = mb[i];
        float    v = wrow[i];
#pragma unroll
        for (int r = 0; r < 32; r++)
            if (m & (1u << r)) acc[r] += v;
    }
#pragma unroll
    for (int r = 0; r < 32; r++) s_red[tid * 32 + r] = acc[r];
    __syncthreads();

    // reduce 8 chunks per (o,row), deterministic ascending order
    for (int u = tid; u < OUT_DIM * 32; u += RO_THREADS) {
        int oo  = u >> 5;
        int row = u & 31;
        float s = br[oo];
#pragma unroll
        for (int c = 0; c < 8; c++)
            s += s_red[(oo * 8 + c) * 32 + row];
        rOut[(size_t)(g * TB + row) * OUT_DIM + oo] = s;
    }
}

// ---------------- readout leaky scan + mean + log_softmax ----------------
__global__ void final_k(const float* __restrict__ rIn, const float* __restrict__ tau_mr,
                        float* __restrict__ out) {
    int b = blockIdx.x;
    int o = threadIdx.x;                     // blockDim = 64, only o<35 active
    __shared__ float sv[64];
    __shared__ float s_mx, s_ls;
    float acc = 0.f;
    if (o < OUT_DIM) {
        float alpha = 1.f / (1.f + expf(-tau_mr[o]));
        float oma = 1.f - alpha;
        float mr = 0.f;
        for (int t = 0; t < T_STEPS; t++) {
            mr = mr * alpha + oma * rIn[(size_t)(t * 64 + b) * OUT_DIM + o];
            acc += mr;
        }
        acc /= (float)T_STEPS;
    }
    sv[o] = (o < OUT_DIM) ? acc : -1e30f;
    __syncthreads();
    if (o == 0) {
        float m = -1e30f;
        for (int i = 0; i < OUT_DIM; i++) m = fmaxf(m, sv[i]);
        float s = 0.f;
        for (int i = 0; i < OUT_DIM; i++) s += expf(sv[i] - m);
        s_mx = m; s_ls = logf(s);
    }
    __syncthreads();
    if (o < OUT_DIM) out[b * OUT_DIM + o] = sv[o] - s_mx - s_ls;
}

// ---------------- launch ----------------
extern "C" void kernel_launch(void* const* d_in, const int* in_sizes, int n_in,
                              void* d_out, int out_size) {
    (void)in_sizes; (void)n_in; (void)out_size;
    const float* x   = (const float*)d_in[0];
    const float* w1  = (const float*)d_in[1];
    const float* b1  = (const float*)d_in[2];
    const float* tm1 = (const float*)d_in[3];
    const float* tn1 = (const float*)d_in[4];
    const float* w2  = (const float*)d_in[5];
    const float* b2  = (const float*)d_in[6];
    const float* tm2 = (const float*)d_in[7];
    const float* tn2 = (const float*)d_in[8];
    const float* w3  = (const float*)d_in[9];
    const float* b3  = (const float*)d_in[10];
    const float* tm3 = (const float*)d_in[11];
    const float* tn3 = (const float*)d_in[12];
    const float* wr  = (const float*)d_in[13];
    const float* br  = (const float*)d_in[14];
    const float* tmr = (const float*)d_in[15];
    const void*  m1  = d_in[16];
    const void*  m2  = d_in[17];
    const void*  m3  = d_in[18];
    float* out = (float*)d_out;

    void *pD, *pB, *pxT, *pr, *pv1, *pv2, *pv3;
    cudaGetSymbolAddress(&pD,  g_D);
    cudaGetSymbolAddress(&pB,  g_bits);
    cudaGetSymbolAddress(&pxT, g_xT);
    cudaGetSymbolAddress(&pr,  g_r);
    cudaGetSymbolAddress(&pv1, g_pv1);
    cudaGetSymbolAddress(&pv2, g_pv2);
    cudaGetSymbolAddress(&pv3, g_pv3);

    // 1) mask dtype + merged CSR build
    detect_mask<<<1, 32>>>(m1);
    build_all<<<3 * NCOLS * 32 / 256, 256>>>(m1, w1, m2, w2, m3, w3,
                                             (uint2*)pv1, (uint2*)pv2, (uint2*)pv3);

    // 2) input transpose
    transpose_x<<<(ROWS * IN_DIM + 255) / 256, 256>>>(x, (float*)pxT);

    dim3 gf(NCOLS / JT, GROUPS);
    dim3 gb(NCOLS / 512, GROUPS);

    // 3) layer 1 (float input, warp-uniform j) -> spike bitmasks
    gemm_float<<<gf, 256>>>((const float*)pxT, (const uint4*)pv1, b1, (float*)pD);
    scan_bits<<<(BSZ * HID) / 256, 256>>>((const float*)pD, tm1, tn1, (unsigned*)pB);

    // 4) layer 2 (bitmask input) -> spike bitmasks
    gemm_bits<<<gb, 256>>>((const unsigned*)pB, (const uint4*)pv2, b2, (float*)pD);
    scan_bits<<<(BSZ * HID) / 256, 256>>>((const float*)pD, tm2, tn2, (unsigned*)pB);

    // 5) layer 3 (bitmask input) -> spike bitmasks
    gemm_bits<<<gb, 256>>>((const unsigned*)pB, (const uint4*)pv3, b3, (float*)pD);
    scan_bits<<<(BSZ * HID) / 256, 256>>>((const float*)pD, tm3, tn3, (unsigned*)pB);

    // 6) readout from bits + final scan + log_softmax
    readout_bits<<<GROUPS, RO_THREADS>>>((const unsigned*)pB, wr, br, (float*)pr);
    final_k<<<BSZ, 64>>>((const float*)pr, tmr, out);
}